// round 15
// baseline (speedup 1.0000x reference)
#include <cuda_runtime.h>
#include <math.h>

// ---------------- problem constants ----------------
#define BB   2
#define SS   1024
#define DD   768
#define HH   12
#define DH   64
#define DM   3072
#define VV   50257
#define LL   2
#define TOK  (BB*SS)          // 2048
#define EPSF 1e-5f

// ---------------- scratch (device globals; no allocation allowed) ----------------
__device__ float g_res  [TOK*DD];
__device__ float g_x    [TOK*DD];
__device__ float g_qkv  [TOK*3*DD];
__device__ float g_scores[(size_t)BB*HH*SS*SS];   // 100.7 MB
__device__ float g_inter[TOK*DD];
__device__ float g_h1   [TOK*DM];

// ---------------- f32x2 packed-FMA helpers (Blackwell) ----------------
typedef unsigned long long u64;

__device__ __forceinline__ u64 pack2(float x, float y) {
    u64 r;
    asm("mov.b64 %0, {%1, %2};" : "=l"(r) : "r"(__float_as_uint(x)), "r"(__float_as_uint(y)));
    return r;
}
__device__ __forceinline__ void unpack2(u64 v, float& x, float& y) {
    unsigned lo, hi;
    asm("mov.b64 {%0, %1}, %2;" : "=r"(lo), "=r"(hi) : "l"(v));
    x = __uint_as_float(lo); y = __uint_as_float(hi);
}
__device__ __forceinline__ u64 ffma2(u64 a, u64 b, u64 c) {
    u64 d;
    asm("fma.rn.f32x2 %0, %1, %2, %3;" : "=l"(d) : "l"(a), "l"(b), "l"(c));
    return d;
}

// ---------------- generic tiled GEMM ----------------
// C[M,N] = scale * (A[M,K] @ opB) (+bias[N]) (gelu) (+resid[M,N]) ; opB = B^T (B is [N,K]) when BT,
// else B is [K,N]. Batched over blockIdx.z with two-level offsets (z = zb*bdiv + zh).
// BM=128, BN=64, BK=16, 256 threads, thread tile 8x4 held as f32x2 pairs along M.
#define BM 128
#define BN 64
#define BK 16

template<bool BT, bool HAS_BIAS, bool HAS_RES, bool HAS_GELU>
__global__ __launch_bounds__(256)
void gemm_kernel(const float* __restrict__ A, const float* __restrict__ Bm,
                 const float* __restrict__ bias, const float* __restrict__ resid,
                 float* __restrict__ C,
                 int M, int N, int K, int lda, int ldb, int ldc,
                 int bdiv,
                 long long sA1, long long sA2,
                 long long sB1, long long sB2,
                 long long sC1, long long sC2,
                 float scale)
{
    __shared__ float As[BK][BM + 4];   // +4 pad keeps 16B alignment, kills most store conflicts
    __shared__ float Bs[BK][BN + 4];

    const int z  = blockIdx.z;
    const int zb = z / bdiv;
    const int zh = z - zb * bdiv;
    A  += (size_t)(zb * sA1 + zh * sA2);
    Bm += (size_t)(zb * sB1 + zh * sB2);
    C  += (size_t)(zb * sC1 + zh * sC2);
    const float* R = resid;
    if (HAS_RES) R += (size_t)(zb * sC1 + zh * sC2);

    const int mBase = blockIdx.y * BM;
    const int nBase = blockIdx.x * BN;
    const int tid = threadIdx.x;
    const int tx = tid & 15;       // N direction (16)
    const int ty = tid >> 4;       // M direction (16)

    u64 acc[4][4];
    #pragma unroll
    for (int p = 0; p < 4; ++p)
        #pragma unroll
        for (int j = 0; j < 4; ++j) acc[p][j] = 0ULL;

    const int aRow = tid >> 2;          // 0..63
    const int aCol = (tid & 3) * 4;     // 0,4,8,12

    for (int k0 = 0; k0 < K; k0 += BK) {
        // ---- load A tile (M always multiple of 128, K multiple of 16) ----
        #pragma unroll
        for (int it = 0; it < 2; ++it) {
            int ar = aRow + it * 64;
            float4 v = *(const float4*)(A + (size_t)(mBase + ar) * lda + k0 + aCol);
            As[aCol + 0][ar] = v.x;
            As[aCol + 1][ar] = v.y;
            As[aCol + 2][ar] = v.z;
            As[aCol + 3][ar] = v.w;
        }
        // ---- load B tile ----
        if (BT) {
            int gn = nBase + aRow;
            float4 v = make_float4(0.f, 0.f, 0.f, 0.f);
            if (gn < N) v = *(const float4*)(Bm + (size_t)gn * ldb + k0 + aCol);
            Bs[aCol + 0][aRow] = v.x;
            Bs[aCol + 1][aRow] = v.y;
            Bs[aCol + 2][aRow] = v.z;
            Bs[aCol + 3][aRow] = v.w;
        } else {
            int bk = tid >> 4;             // 0..15
            int bn = (tid & 15) * 4;       // 0..60
            int gn = nBase + bn;
            float4 v = make_float4(0.f, 0.f, 0.f, 0.f);
            if (gn < N) v = *(const float4*)(Bm + (size_t)(k0 + bk) * ldb + gn);
            *(float4*)&Bs[bk][bn] = v;
        }
        __syncthreads();

        // ---- compute ----
        #pragma unroll
        for (int k = 0; k < BK; ++k) {
            const u64* ar = (const u64*)&As[k][ty * 8];     // 4 M-pairs straight from SMEM
            u64 ap0 = ar[0], ap1 = ar[1], ap2 = ar[2], ap3 = ar[3];
            float4 bv = *(const float4*)&Bs[k][tx * 4];
            u64 bb0 = pack2(bv.x, bv.x);
            u64 bb1 = pack2(bv.y, bv.y);
            u64 bb2 = pack2(bv.z, bv.z);
            u64 bb3 = pack2(bv.w, bv.w);
            acc[0][0] = ffma2(ap0, bb0, acc[0][0]);
            acc[0][1] = ffma2(ap0, bb1, acc[0][1]);
            acc[0][2] = ffma2(ap0, bb2, acc[0][2]);
            acc[0][3] = ffma2(ap0, bb3, acc[0][3]);
            acc[1][0] = ffma2(ap1, bb0, acc[1][0]);
            acc[1][1] = ffma2(ap1, bb1, acc[1][1]);
            acc[1][2] = ffma2(ap1, bb2, acc[1][2]);
            acc[1][3] = ffma2(ap1, bb3, acc[1][3]);
            acc[2][0] = ffma2(ap2, bb0, acc[2][0]);
            acc[2][1] = ffma2(ap2, bb1, acc[2][1]);
            acc[2][2] = ffma2(ap2, bb2, acc[2][2]);
            acc[2][3] = ffma2(ap2, bb3, acc[2][3]);
            acc[3][0] = ffma2(ap3, bb0, acc[3][0]);
            acc[3][1] = ffma2(ap3, bb1, acc[3][1]);
            acc[3][2] = ffma2(ap3, bb2, acc[3][2]);
            acc[3][3] = ffma2(ap3, bb3, acc[3][3]);
        }
        __syncthreads();
    }

    // ---- epilogue ----
    float o[8][4];
    #pragma unroll
    for (int p = 0; p < 4; ++p)
        #pragma unroll
        for (int j = 0; j < 4; ++j)
            unpack2(acc[p][j], o[2 * p][j], o[2 * p + 1][j]);

    const int gn0 = nBase + tx * 4;
    float bv4[4] = {0.f, 0.f, 0.f, 0.f};
    if (HAS_BIAS) {
        #pragma unroll
        for (int j = 0; j < 4; ++j)
            if (gn0 + j < N) bv4[j] = bias[gn0 + j];
    }
    #pragma unroll
    for (int i = 0; i < 8; ++i) {
        const int gm = mBase + ty * 8 + i;
        float* crow = C + (size_t)gm * ldc;
        const float* rrow = HAS_RES ? (R + (size_t)gm * ldc) : nullptr;
        #pragma unroll
        for (int j = 0; j < 4; ++j) {
            int gn = gn0 + j;
            if (gn < N) {
                float v = o[i][j] * scale;
                if (HAS_BIAS) v += bv4[j];
                if (HAS_GELU) v = 0.5f * v * (1.0f + erff(v * 0.70710678118654752f));
                if (HAS_RES)  v += rrow[gn];
                crow[gn] = v;
            }
        }
    }
}

// ---------------- LayerNorm (faithful: divide by (std + eps)) ----------------
__global__ __launch_bounds__(256)
void ln_kernel(const float* __restrict__ x, const float* __restrict__ w,
               const float* __restrict__ b, float* __restrict__ y)
{
    const int row = blockIdx.x;
    const float* xr = x + (size_t)row * DD;
    float* yr = y + (size_t)row * DD;
    const int tid = threadIdx.x;
    float s = 0.f, s2 = 0.f;
    for (int i = tid; i < DD; i += 256) {
        float v = xr[i];
        s += v;
        s2 = fmaf(v, v, s2);
    }
    __shared__ float sh1[256], sh2[256];
    sh1[tid] = s; sh2[tid] = s2;
    __syncthreads();
    for (int st = 128; st > 0; st >>= 1) {
        if (tid < st) { sh1[tid] += sh1[tid + st]; sh2[tid] += sh2[tid + st]; }
        __syncthreads();
    }
    const float mean = sh1[0] * (1.f / DD);
    float var = sh2[0] * (1.f / DD) - mean * mean;
    var = var > 0.f ? var : 0.f;
    const float inv = 1.f / (sqrtf(var) + EPSF);
    for (int i = tid; i < DD; i += 256)
        yr[i] = w[i] * ((xr[i] - mean) * inv) + b[i];
}

// ---------------- causal softmax over score rows ----------------
__global__ __launch_bounds__(256)
void softmax_kernel(float* __restrict__ sc)
{
    const int row = blockIdx.x;            // z*S + q
    const int q = row & (SS - 1);
    float* p = sc + (size_t)row * SS;
    const int tid = threadIdx.x;
    __shared__ float sh[256];

    float mx = -3.4e38f;
    for (int k = tid; k < SS; k += 256)
        if (k <= q) mx = fmaxf(mx, p[k]);
    sh[tid] = mx; __syncthreads();
    for (int st = 128; st > 0; st >>= 1) {
        if (tid < st) sh[tid] = fmaxf(sh[tid], sh[tid + st]);
        __syncthreads();
    }
    mx = sh[0]; __syncthreads();

    float sum = 0.f;
    for (int k = tid; k < SS; k += 256) {
        if (k <= q) { float e = __expf(p[k] - mx); p[k] = e; sum += e; }
        else p[k] = 0.f;
    }
    sh[tid] = sum; __syncthreads();
    for (int st = 128; st > 0; st >>= 1) {
        if (tid < st) sh[tid] += sh[tid + st];
        __syncthreads();
    }
    const float inv = 1.f / sh[0];
    for (int k = tid; k < SS; k += 256)
        if (k <= q) p[k] *= inv;
}

// ---------------- embedding gather + positional ----------------
__global__ __launch_bounds__(256)
void embed_kernel(const int* __restrict__ ids, const float* __restrict__ emb,
                  const float* __restrict__ pos, float* __restrict__ res)
{
    int idx = blockIdx.x * 256 + threadIdx.x;
    if (idx < TOK * DD) {
        int t = idx / DD;
        int d = idx - t * DD;
        int s = t & (SS - 1);
        res[idx] = emb[(size_t)ids[t] * DD + d] + pos[(size_t)s * DD + d];
    }
}

// ---------------- launcher ----------------
extern "C" void kernel_launch(void* const* d_in, const int* in_sizes, int n_in,
                              void* d_out, int out_size)
{
    const int*   ids    = (const int*)  d_in[0];
    const float* embed  = (const float*)d_in[1];
    const float* pos    = (const float*)d_in[2];
    const float* ln1w   = (const float*)d_in[3];
    const float* ln1b   = (const float*)d_in[4];
    const float* W_attn = (const float*)d_in[5];
    const float* b_attn = (const float*)d_in[6];
    const float* W_O    = (const float*)d_in[7];
    const float* b_O    = (const float*)d_in[8];
    const float* ln2w   = (const float*)d_in[9];
    const float* ln2b   = (const float*)d_in[10];
    const float* W_in   = (const float*)d_in[11];
    const float* b_in   = (const float*)d_in[12];
    const float* W_out  = (const float*)d_in[13];
    const float* b_out  = (const float*)d_in[14];
    const float* lnfw   = (const float*)d_in[15];
    const float* lnfb   = (const float*)d_in[16];
    const float* W_U    = (const float*)d_in[17];
    const float* b_U    = (const float*)d_in[18];
    float* out = (float*)d_out;

    float *res, *x, *qkv, *sc, *inter, *h1;
    cudaGetSymbolAddress((void**)&res,   g_res);
    cudaGetSymbolAddress((void**)&x,     g_x);
    cudaGetSymbolAddress((void**)&qkv,   g_qkv);
    cudaGetSymbolAddress((void**)&sc,    g_scores);
    cudaGetSymbolAddress((void**)&inter, g_inter);
    cudaGetSymbolAddress((void**)&h1,    g_h1);

    embed_kernel<<<(TOK * DD + 255) / 256, 256>>>(ids, embed, pos, res);

    const long long SSll = (long long)SS * SS;

    for (int l = 0; l < LL; ++l) {
        // LN1
        ln_kernel<<<TOK, 256>>>(res, ln1w + l * DD, ln1b + l * DD, x);

        // QKV: [2048,2304] = x @ W_attn^T + b_attn
        gemm_kernel<true, true, false, false><<<dim3(3 * DD / BN, TOK / BM, 1), 256>>>(
            x, W_attn + (size_t)l * 3 * DD * DD, b_attn + l * 3 * DD, nullptr, qkv,
            TOK, 3 * DD, DD, DD, DD, 3 * DD,
            1, 0, 0, 0, 0, 0, 0, 1.0f);

        // scores[z,q,k] = (Q @ K^T) / 8, z = b*H + h (batched)
        gemm_kernel<true, false, false, false><<<dim3(SS / BN, SS / BM, BB * HH), 256>>>(
            qkv, qkv + DD, nullptr, nullptr, sc,
            SS, SS, DH, 3 * DD, 3 * DD, SS,
            HH,
            (long long)SS * 3 * DD, DH,
            (long long)SS * 3 * DD, DH,
            (long long)HH * SSll, SSll,
            0.125f);

        softmax_kernel<<<BB * HH * SS, 256>>>(sc);

        // inter[b,q,h*64+d] = P @ V   (B not transposed)
        gemm_kernel<false, false, false, false><<<dim3(1, SS / BM, BB * HH), 256>>>(
            sc, qkv + 2 * DD, nullptr, nullptr, inter,
            SS, DH, SS, SS, 3 * DD, DD,
            HH,
            (long long)HH * SSll, SSll,
            (long long)SS * 3 * DD, DH,
            (long long)SS * DD, DH,
            1.0f);

        // O projection + residual (in-place on res)
        gemm_kernel<true, true, true, false><<<dim3(DD / BN, TOK / BM, 1), 256>>>(
            inter, W_O + (size_t)l * DD * DD, b_O + l * DD, res, res,
            TOK, DD, DD, DD, DD, DD,
            1, 0, 0, 0, 0, 0, 0, 1.0f);

        // LN2
        ln_kernel<<<TOK, 256>>>(res, ln2w + l * DD, ln2b + l * DD, x);

        // MLP in: gelu(x @ W_in^T + b_in)
        gemm_kernel<true, true, false, true><<<dim3(DM / BN, TOK / BM, 1), 256>>>(
            x, W_in + (size_t)l * DM * DD, b_in + l * DM, nullptr, h1,
            TOK, DM, DD, DD, DD, DM,
            1, 0, 0, 0, 0, 0, 0, 1.0f);

        // MLP out + residual (in-place on res)
        gemm_kernel<true, true, true, false><<<dim3(DD / BN, TOK / BM, 1), 256>>>(
            h1, W_out + (size_t)l * DD * DM, b_out + l * DD, res, res,
            TOK, DD, DM, DM, DM, DD,
            1, 0, 0, 0, 0, 0, 0, 1.0f);
    }

    // final LN
    ln_kernel<<<TOK, 256>>>(res, lnfw, lnfb, x);

    // un-embedding: out[2048, 50257] = x @ W_U^T + b_U
    gemm_kernel<true, true, false, false><<<dim3((VV + BN - 1) / BN, TOK / BM, 1), 256>>>(
        x, W_U, b_U, nullptr, out,
        TOK, VV, DD, DD, DD, VV,
        1, 0, 0, 0, 0, 0, 0, 1.0f);
}